// round 2
// baseline (speedup 1.0000x reference)
#include <cuda_runtime.h>
#include <cstdint>

#define MAX_NODES 100000
#define F1 32
#define F2 16
#define F3 2

// Scratch (device globals; no allocation allowed)
__device__ __align__(256) float g_y1[MAX_NODES * F1];  // z @ W_rel1 (per-source projected features)
__device__ __align__(256) float g_h1[MAX_NODES * F1];  // accumulator: root + b, then += scatter
__device__ __align__(256) float g_y2[MAX_NODES * F2];
__device__ __align__(256) float g_h2[MAX_NODES * F2];
__device__ __align__(256) float g_y3[MAX_NODES * F3];
__device__ __align__(256) float g_h3[MAX_NODES * F3];

// ---------------------------------------------------------------------------
// Dense transform: for each node,
//   y[node] = act(x[node]) @ Wrel          (to be scattered along edges)
//   h[node] = act(x[node]) @ Wroot + b     (accumulator init = root term)
// Weights staged in shared memory; all lanes read the same SMEM address per
// FMA -> broadcast, conflict-free.
// ---------------------------------------------------------------------------
template <int FIN, int FOUT, bool RELU>
__global__ void transform_k(const float* __restrict__ x,
                            const float* __restrict__ Wrel,
                            const float* __restrict__ Wroot,
                            const float* __restrict__ b,
                            float* __restrict__ y,
                            float* __restrict__ h,
                            int n) {
    __shared__ float s_rel[FIN * FOUT];
    __shared__ float s_root[FIN * FOUT];
    __shared__ float s_b[FOUT];
    for (int i = threadIdx.x; i < FIN * FOUT; i += blockDim.x) {
        s_rel[i]  = Wrel[i];
        s_root[i] = Wroot[i];
    }
    for (int i = threadIdx.x; i < FOUT; i += blockDim.x) s_b[i] = b[i];
    __syncthreads();

    int node = blockIdx.x * blockDim.x + threadIdx.x;
    if (node >= n) return;

    float accR[FOUT];
    float accO[FOUT];
#pragma unroll
    for (int j = 0; j < FOUT; j++) { accR[j] = 0.f; accO[j] = 0.f; }

    const float4* xr = reinterpret_cast<const float4*>(x + (size_t)node * FIN);
#pragma unroll
    for (int kk = 0; kk < FIN / 4; kk++) {
        float4 xv = __ldg(xr + kk);
        float xs[4] = {xv.x, xv.y, xv.z, xv.w};
#pragma unroll
        for (int q = 0; q < 4; q++) {
            float v = RELU ? fmaxf(xs[q], 0.f) : xs[q];
            const int k = kk * 4 + q;
#pragma unroll
            for (int j = 0; j < FOUT; j++) {
                accR[j] = fmaf(v, s_rel[k * FOUT + j], accR[j]);
                accO[j] = fmaf(v, s_root[k * FOUT + j], accO[j]);
            }
        }
    }

    float* yo = y + (size_t)node * FOUT;
    float* ho = h + (size_t)node * FOUT;
#pragma unroll
    for (int j = 0; j < FOUT; j++) {
        yo[j] = accR[j];
        ho[j] = accO[j] + s_b[j];
    }
}

// ---------------------------------------------------------------------------
// Edge scatter: h[dst] += y[src], vectorized float4 per lane.
// F/4 consecutive lanes cover one row -> gather is a coalesced read;
// scatter uses red.global.add.v4.f32 (fire-and-forget, sm_90+).
// edge_index is int32 (JAX default x64-disabled downcasts the declared int64).
// ---------------------------------------------------------------------------
template <int F>
__global__ void scatter_k(const int* __restrict__ ei,
                          const float* __restrict__ y,
                          float* __restrict__ h,
                          int e) {
    constexpr int CH = F / 4;  // float4 chunks per row
    int t = blockIdx.x * blockDim.x + threadIdx.x;
    if (t >= e * CH) return;
    int edge = t / CH;
    int c    = t % CH;
    int src = ei[edge];
    int dst = ei[e + edge];
    const float4 v = *reinterpret_cast<const float4*>(y + (size_t)src * F + c * 4);
    float* p = h + (size_t)dst * F + c * 4;
    asm volatile("red.global.add.v4.f32 [%0], {%1, %2, %3, %4};"
                 :: "l"(p), "f"(v.x), "f"(v.y), "f"(v.z), "f"(v.w)
                 : "memory");
}

// Final layer scatter: 2 floats per edge via red.v2.
__global__ void scatter2_k(const int* __restrict__ ei,
                           const float* __restrict__ y,
                           float* __restrict__ h,
                           int e) {
    int t = blockIdx.x * blockDim.x + threadIdx.x;
    if (t >= e) return;
    int src = ei[t];
    int dst = ei[e + t];
    const float2 v = *reinterpret_cast<const float2*>(y + 2 * (size_t)src);
    float* p = h + 2 * (size_t)dst;
    asm volatile("red.global.add.v2.f32 [%0], {%1, %2};"
                 :: "l"(p), "f"(v.x), "f"(v.y)
                 : "memory");
}

// 2-class softmax over h3 -> out.
__global__ void softmax_k(const float* __restrict__ h, float* __restrict__ out, int n) {
    int i = blockIdx.x * blockDim.x + threadIdx.x;
    if (i >= n) return;
    float2 v = *reinterpret_cast<const float2*>(h + 2 * (size_t)i);
    float m  = fmaxf(v.x, v.y);
    float ea = __expf(v.x - m);
    float eb = __expf(v.y - m);
    float inv = 1.0f / (ea + eb);
    reinterpret_cast<float2*>(out)[i] = make_float2(ea * inv, eb * inv);
}

extern "C" void kernel_launch(void* const* d_in, const int* in_sizes, int n_in,
                              void* d_out, int out_size) {
    const float* z      = (const float*)d_in[0];
    const int*   ei     = (const int*)d_in[1];   // int32 (JAX x64 disabled)
    const float* Wrel1  = (const float*)d_in[2];
    const float* Wroot1 = (const float*)d_in[3];
    const float* b1     = (const float*)d_in[4];
    const float* Wrel2  = (const float*)d_in[5];
    const float* Wroot2 = (const float*)d_in[6];
    const float* b2     = (const float*)d_in[7];
    const float* Wrel3  = (const float*)d_in[8];
    const float* Wroot3 = (const float*)d_in[9];
    const float* b3     = (const float*)d_in[10];

    const int n = in_sizes[0] / 64;   // 100000
    const int e = in_sizes[1] / 2;    // 1600000

    float *y1, *h1, *y2, *h2, *y3, *h3;
    cudaGetSymbolAddress((void**)&y1, g_y1);
    cudaGetSymbolAddress((void**)&h1, g_h1);
    cudaGetSymbolAddress((void**)&y2, g_y2);
    cudaGetSymbolAddress((void**)&h2, g_h2);
    cudaGetSymbolAddress((void**)&y3, g_y3);
    cudaGetSymbolAddress((void**)&h3, g_h3);

    const int TB = 128;
    const int nodeBlocks = (n + TB - 1) / TB;

    // Layer 1
    transform_k<64, F1, false><<<nodeBlocks, TB>>>(z, Wrel1, Wroot1, b1, y1, h1, n);
    {
        int total = e * (F1 / 4);
        scatter_k<F1><<<(total + 255) / 256, 256>>>(ei, y1, h1, e);
    }
    // Layer 2 (ReLU applied on read of h1)
    transform_k<F1, F2, true><<<nodeBlocks, TB>>>(h1, Wrel2, Wroot2, b2, y2, h2, n);
    {
        int total = e * (F2 / 4);
        scatter_k<F2><<<(total + 255) / 256, 256>>>(ei, y2, h2, e);
    }
    // Layer 3
    transform_k<F2, F3, true><<<nodeBlocks, TB>>>(h2, Wrel3, Wroot3, b3, y3, h3, n);
    scatter2_k<<<(e + 255) / 256, 256>>>(ei, y3, h3, e);

    // Softmax -> output
    softmax_k<<<nodeBlocks, TB>>>(h3, (float*)d_out, n);
}